// round 1
// baseline (speedup 1.0000x reference)
#include <cuda_runtime.h>
#include <math.h>

#define G    1024
#define NSV  16
#define NTRK 64
#define HID  128
#define KNN  8

// ---------------- scratch (static device globals: no allocation) ----------------
__device__ float g_sv [G*NSV *HID];   // 8 MB
__device__ float g_trk[G*NTRK*HID];   // 32 MB
__device__ float g_U  [G*NTRK*HID];   // 32 MB (reused for U1 then U2)
__device__ float g_V1 [G*NSV *HID];   // 8 MB
__device__ float g_f1 [G*NTRK*HID];   // 32 MB
__device__ float g_V2 [G*NTRK*HID];   // 32 MB
__device__ float g_f2 [G*NTRK*HID];   // 32 MB

__device__ __forceinline__ float eluf(float x) { return x > 0.f ? x : expm1f(x); }

// ---------------- fused 2-layer MLP: Y = relu( elu(X@W1+b1) @ W2 + b2 ) ----------------
// X: M x IN_DIM, W1: IN_DIM x 128, W2: 128 x 128. Block: 64 rows, 256 threads.
template<int IN_DIM>
__global__ __launch_bounds__(256)
void mlp2_kernel(const float* __restrict__ X,
                 const float* __restrict__ W1, const float* __restrict__ b1,
                 const float* __restrict__ W2, const float* __restrict__ b2,
                 float* __restrict__ Y)
{
    __shared__ float Hs[64*132];
    __shared__ float Bs[16*132];
    const int bm  = blockIdx.x * 64;
    const int tid = threadIdx.x;
    const int tx  = tid & 15, ty = tid >> 4;

    // layer 1: H = elu(X@W1 + b1), 64x128
    #pragma unroll
    for (int e = 0; e < 32; e++) {
        int idx = tid + e * 256;          // 0..8191
        int r = idx >> 7, c = idx & 127;
        float acc = b1[c];
        #pragma unroll
        for (int d = 0; d < IN_DIM; d++)
            acc += X[(bm + r) * IN_DIM + d] * W1[d * 128 + c];
        Hs[r * 132 + c] = eluf(acc);
    }
    __syncthreads();

    // layer 2 GEMM: 64x128 @ 128x128
    float acc[4][8];
    #pragma unroll
    for (int i = 0; i < 4; i++)
        #pragma unroll
        for (int j = 0; j < 8; j++) acc[i][j] = 0.f;

    for (int k0 = 0; k0 < 128; k0 += 16) {
        #pragma unroll
        for (int e = 0; e < 8; e++) {
            int idx = tid + e * 256;      // 0..2047
            int kk = idx >> 7, c = idx & 127;
            Bs[kk * 132 + c] = W2[(k0 + kk) * 128 + c];
        }
        __syncthreads();
        #pragma unroll
        for (int kk = 0; kk < 16; kk++) {
            float a[4], b[8];
            #pragma unroll
            for (int i = 0; i < 4; i++) a[i] = Hs[(ty * 4 + i) * 132 + k0 + kk];
            #pragma unroll
            for (int j = 0; j < 8; j++) b[j] = Bs[kk * 132 + tx * 8 + j];
            #pragma unroll
            for (int i = 0; i < 4; i++)
                #pragma unroll
                for (int j = 0; j < 8; j++) acc[i][j] += a[i] * b[j];
        }
        __syncthreads();
    }
    #pragma unroll
    for (int i = 0; i < 4; i++) {
        int r = bm + ty * 4 + i;
        float4 v0, v1;
        int cb = tx * 8;
        v0.x = fmaxf(acc[i][0] + b2[cb+0], 0.f);
        v0.y = fmaxf(acc[i][1] + b2[cb+1], 0.f);
        v0.z = fmaxf(acc[i][2] + b2[cb+2], 0.f);
        v0.w = fmaxf(acc[i][3] + b2[cb+3], 0.f);
        v1.x = fmaxf(acc[i][4] + b2[cb+4], 0.f);
        v1.y = fmaxf(acc[i][5] + b2[cb+5], 0.f);
        v1.z = fmaxf(acc[i][6] + b2[cb+6], 0.f);
        v1.w = fmaxf(acc[i][7] + b2[cb+7], 0.f);
        *(float4*)&Y[r * 128 + cb]     = v0;
        *(float4*)&Y[r * 128 + cb + 4] = v1;
    }
}

// ---------------- GEMM with decomposed weight ----------------
// MODE 0: Weff[k][c] = W[k][c] - W[128+k][c]   (the "xi" transform A)
// MODE 1: Weff[k][c] = W[128+k][c]             (the "xj" transform B)
// Y = X @ Weff, X: M x 128 (M % 64 == 0)
template<int MODE>
__global__ __launch_bounds__(256)
void gemm_dec_kernel(const float* __restrict__ X, const float* __restrict__ W,
                     float* __restrict__ Y)
{
    __shared__ float As[64*17];
    __shared__ float Bs[16*132];
    const int bm  = blockIdx.x * 64;
    const int tid = threadIdx.x;
    const int tx  = tid & 15, ty = tid >> 4;

    float acc[4][8];
    #pragma unroll
    for (int i = 0; i < 4; i++)
        #pragma unroll
        for (int j = 0; j < 8; j++) acc[i][j] = 0.f;

    for (int k0 = 0; k0 < 128; k0 += 16) {
        #pragma unroll
        for (int e = 0; e < 4; e++) {
            int idx = tid + e * 256;      // 0..1023
            int r = idx >> 4, kk = idx & 15;
            As[r * 17 + kk] = X[(bm + r) * 128 + k0 + kk];
        }
        #pragma unroll
        for (int e = 0; e < 8; e++) {
            int idx = tid + e * 256;      // 0..2047
            int kk = idx >> 7, c = idx & 127;
            int k = k0 + kk;
            float w = (MODE == 0) ? (W[k * 128 + c] - W[(k + 128) * 128 + c])
                                  : W[(k + 128) * 128 + c];
            Bs[kk * 132 + c] = w;
        }
        __syncthreads();
        #pragma unroll
        for (int kk = 0; kk < 16; kk++) {
            float a[4], b[8];
            #pragma unroll
            for (int i = 0; i < 4; i++) a[i] = As[(ty * 4 + i) * 17 + kk];
            #pragma unroll
            for (int j = 0; j < 8; j++) b[j] = Bs[kk * 132 + tx * 8 + j];
            #pragma unroll
            for (int i = 0; i < 4; i++)
                #pragma unroll
                for (int j = 0; j < 8; j++) acc[i][j] += a[i] * b[j];
        }
        __syncthreads();
    }
    #pragma unroll
    for (int i = 0; i < 4; i++) {
        int r = bm + ty * 4 + i;
        float4 v0 = {acc[i][0], acc[i][1], acc[i][2], acc[i][3]};
        float4 v1 = {acc[i][4], acc[i][5], acc[i][6], acc[i][7]};
        *(float4*)&Y[r * 128 + tx * 8]     = v0;
        *(float4*)&Y[r * 128 + tx * 8 + 4] = v1;
    }
}

// ---------------- edge conv: kNN + gather-max + ELU ----------------
// One block per graph. dst features always the 64 tracks.
// out[i][c] = elu( U[i][c] + bias[c] + max_n V[knn(i,n)][c] )
template<int NSRC>
__global__ __launch_bounds__(256)
void edgeconv_kernel(const float* __restrict__ dstF, const float* __restrict__ srcF,
                     const float* __restrict__ U,    const float* __restrict__ V,
                     const float* __restrict__ bias, float* __restrict__ out)
{
    extern __shared__ float sm[];
    float* dsh = sm;                      // 64 * 132
    float* ssh = dsh + 64 * 132;          // NSRC * 132
    float* vsh = ssh + NSRC * 132;        // NSRC * 132
    float* d2s = vsh + NSRC * 132;        // 64 * (NSRC+1)
    float* dn2 = d2s + 64 * (NSRC + 1);   // 64
    float* sn2 = dn2 + 64;                // NSRC
    float* bsh = sn2 + NSRC;              // 128
    int*  idxs = (int*)(bsh + 128);       // 64 * 8

    const int g   = blockIdx.x;
    const int tid = threadIdx.x;
    const float* dg = dstF + (size_t)g * 64   * 128;
    const float* sg = srcF + (size_t)g * NSRC * 128;
    const float* Vg = V    + (size_t)g * NSRC * 128;
    const float* Ug = U    + (size_t)g * 64   * 128;

    for (int idx = tid; idx < 64 * 128; idx += 256) {
        int r = idx >> 7, c = idx & 127;
        dsh[r * 132 + c] = dg[idx];
    }
    for (int idx = tid; idx < NSRC * 128; idx += 256) {
        int r = idx >> 7, c = idx & 127;
        ssh[r * 132 + c] = sg[idx];
        vsh[r * 132 + c] = Vg[idx];
    }
    if (tid < 128) bsh[tid] = bias[tid];
    __syncthreads();

    // squared norms
    if (tid < 64) {
        float s = 0.f;
        #pragma unroll 8
        for (int d = 0; d < 128; d++) { float v = dsh[tid * 132 + d]; s += v * v; }
        dn2[tid] = s;
    } else if (tid < 64 + NSRC) {
        int j = tid - 64;
        float s = 0.f;
        #pragma unroll 8
        for (int d = 0; d < 128; d++) { float v = ssh[j * 132 + d]; s += v * v; }
        sn2[j] = s;
    }
    __syncthreads();

    // pairwise squared distances
    for (int p = tid; p < 64 * NSRC; p += 256) {
        int i = p / NSRC, j = p % NSRC;
        float dot = 0.f;
        #pragma unroll 8
        for (int d = 0; d < 128; d++) dot += dsh[i * 132 + d] * ssh[j * 132 + d];
        d2s[i * (NSRC + 1) + j] = dn2[i] - 2.f * dot + sn2[j];
    }
    __syncthreads();

    // top-8 smallest per track (tie -> lowest index, matching lax.top_k on -d2)
    if (tid < 64) {
        const float* row = &d2s[tid * (NSRC + 1)];
        unsigned long long used = 0ull;
        #pragma unroll
        for (int n = 0; n < KNN; n++) {
            float best = INFINITY; int bj = 0;
            for (int j = 0; j < NSRC; j++) {
                if ((used >> j) & 1ull) continue;
                float v = row[j];
                if (v < best) { best = v; bj = j; }
            }
            used |= 1ull << bj;
            idxs[tid * 8 + n] = bj;
        }
    }
    __syncthreads();

    // combine: elu(U + b + max_n V[idx_n])  (ELU is monotone -> max first)
    for (int i0 = 0; i0 < 64; i0 += 2) {
        int i = i0 + (tid >> 7);
        int c = tid & 127;
        float u = Ug[i * 128 + c] + bsh[c];
        float vmax = -INFINITY;
        #pragma unroll
        for (int n = 0; n < KNN; n++) {
            int j = idxs[i * 8 + n];
            vmax = fmaxf(vmax, vsh[j * 132 + c]);
        }
        float val = u + vmax;
        out[((size_t)g * 64 + i) * 128 + c] = eluf(val);
    }
}

// ---------------- pooled mean + head MLP + output ----------------
__global__ __launch_bounds__(128)
void head_kernel(const float* __restrict__ f2,
                 const float* __restrict__ Wo1, const float* __restrict__ bo1,
                 const float* __restrict__ Wo2, const float* __restrict__ bo2,
                 const float* __restrict__ Wo3, const float* __restrict__ bo3,
                 const float* __restrict__ Wo4, const float* __restrict__ bo4,
                 float* __restrict__ out, int out_size)
{
    __shared__ float pooled[128];
    __shared__ float h1[64];
    __shared__ float h2[32];
    __shared__ float h3[4];
    const int g = blockIdx.x, tid = threadIdx.x;
    const float* base = f2 + (size_t)g * 64 * 128;

    float s = 0.f;
    #pragma unroll 8
    for (int i = 0; i < 64; i++) s += base[i * 128 + tid];
    pooled[tid] = s * (1.f / 64.f);
    __syncthreads();

    if (tid < 64) {
        float a = bo1[tid];
        #pragma unroll 8
        for (int d = 0; d < 128; d++) a += pooled[d] * Wo1[d * 64 + tid];
        h1[tid] = eluf(a);
    }
    __syncthreads();
    if (tid < 32) {
        float a = bo2[tid];
        #pragma unroll 8
        for (int d = 0; d < 64; d++) a += h1[d] * Wo2[d * 32 + tid];
        h2[tid] = eluf(a);
    }
    __syncthreads();
    if (tid < 4) {
        float a = bo3[tid];
        #pragma unroll
        for (int d = 0; d < 32; d++) a += h2[d] * Wo3[d * 4 + tid];
        h3[tid] = eluf(a);
    }
    __syncthreads();
    if (tid == 0) {
        float a = bo4[0];
        #pragma unroll
        for (int d = 0; d < 4; d++) a += h3[d] * Wo4[d];
        out[g] = a;
        if (out_size >= 2 * G) out[G + g] = (float)g;   // batch = arange(G)
    }
}

// ---------------- launch ----------------
extern "C" void kernel_launch(void* const* d_in, const int* in_sizes, int n_in,
                              void* d_out, int out_size)
{
    const float* x_sv   = (const float*)d_in[0];
    const float* x_trk  = (const float*)d_in[1];
    const float* W_sv1  = (const float*)d_in[2];
    const float* b_sv1  = (const float*)d_in[3];
    const float* W_sv2  = (const float*)d_in[4];
    const float* b_sv2  = (const float*)d_in[5];
    const float* W_trk1 = (const float*)d_in[6];
    const float* b_trk1 = (const float*)d_in[7];
    const float* W_trk2 = (const float*)d_in[8];
    const float* b_trk2 = (const float*)d_in[9];
    const float* W_c1   = (const float*)d_in[10];
    const float* b_c1   = (const float*)d_in[11];
    const float* W_c2   = (const float*)d_in[12];
    const float* b_c2   = (const float*)d_in[13];
    const float* W_o1   = (const float*)d_in[14];
    const float* b_o1   = (const float*)d_in[15];
    const float* W_o2   = (const float*)d_in[16];
    const float* b_o2   = (const float*)d_in[17];
    const float* W_o3   = (const float*)d_in[18];
    const float* b_o3   = (const float*)d_in[19];
    const float* W_o4   = (const float*)d_in[20];
    const float* b_o4   = (const float*)d_in[21];
    float* out = (float*)d_out;

    float *p_sv, *p_trk, *p_U, *p_V1, *p_f1, *p_V2, *p_f2;
    cudaGetSymbolAddress((void**)&p_sv,  g_sv);
    cudaGetSymbolAddress((void**)&p_trk, g_trk);
    cudaGetSymbolAddress((void**)&p_U,   g_U);
    cudaGetSymbolAddress((void**)&p_V1,  g_V1);
    cudaGetSymbolAddress((void**)&p_f1,  g_f1);
    cudaGetSymbolAddress((void**)&p_V2,  g_V2);
    cudaGetSymbolAddress((void**)&p_f2,  g_f2);

    const int smem1 = (64*132 + NSV*132  + NSV*132  + 64*(NSV+1)  + 64 + NSV  + 128) * 4 + 64*8*4;
    const int smem2 = (64*132 + NTRK*132 + NTRK*132 + 64*(NTRK+1) + 64 + NTRK + 128) * 4 + 64*8*4;
    cudaFuncSetAttribute(edgeconv_kernel<NSV>,  cudaFuncAttributeMaxDynamicSharedMemorySize, smem1);
    cudaFuncSetAttribute(edgeconv_kernel<NTRK>, cudaFuncAttributeMaxDynamicSharedMemorySize, smem2);

    // node MLPs
    mlp2_kernel<2><<<G*NSV /64, 256>>>(x_sv,  W_sv1,  b_sv1,  W_sv2,  b_sv2,  p_sv);
    mlp2_kernel<8><<<G*NTRK/64, 256>>>(x_trk, W_trk1, b_trk1, W_trk2, b_trk2, p_trk);

    // conv1: U1 = trk @ (Wc1_top - Wc1_bot), V1 = sv @ Wc1_bot
    gemm_dec_kernel<0><<<G*NTRK/64, 256>>>(p_trk, W_c1, p_U);
    gemm_dec_kernel<1><<<G*NSV /64, 256>>>(p_sv,  W_c1, p_V1);
    edgeconv_kernel<NSV><<<G, 256, smem1>>>(p_trk, p_sv, p_U, p_V1, b_c1, p_f1);

    // conv2: U2 = trk @ (Wc2_top - Wc2_bot), V2 = f1 @ Wc2_bot
    gemm_dec_kernel<0><<<G*NTRK/64, 256>>>(p_trk, W_c2, p_U);
    gemm_dec_kernel<1><<<G*NTRK/64, 256>>>(p_f1,  W_c2, p_V2);
    edgeconv_kernel<NTRK><<<G, 256, smem2>>>(p_trk, p_f1, p_U, p_V2, b_c2, p_f2);

    // head
    head_kernel<<<G, 128>>>(p_f2, W_o1, b_o1, W_o2, b_o2, W_o3, b_o3,
                            W_o4, b_o4, out, out_size);
}

// round 3
// speedup vs baseline: 1.2160x; 1.2160x over previous
#include <cuda_runtime.h>
#include <math.h>
#include <float.h>

#define G    1024
#define NSV  16
#define NTRK 64
#define HID  128
#define KNN  8

typedef unsigned long long u64;

// ---------------- scratch (static device globals: no allocation) ----------------
__device__ float g_sv [G*NSV *HID];   // 8 MB
__device__ float g_trk[G*NTRK*HID];   // 32 MB
__device__ float g_U1 [G*NTRK*HID];   // 32 MB
__device__ float g_U2 [G*NTRK*HID];   // 32 MB
__device__ float g_V1 [G*NSV *HID];   // 8 MB
__device__ float g_V2 [G*NTRK*HID];   // 32 MB
__device__ float g_f1 [G*NTRK*HID];   // 32 MB

__device__ __forceinline__ float eluf(float x) { return x > 0.f ? x : expm1f(x); }

// ---- packed f32x2 helpers ----
__device__ __forceinline__ u64 splat2(float a) {
    u64 r; asm("mov.b64 %0, {%1, %1};" : "=l"(r) : "f"(a)); return r;
}
__device__ __forceinline__ void ffma2(u64& c, u64 a, u64 b) {
    asm("fma.rn.f32x2 %0, %1, %2, %0;" : "+l"(c) : "l"(a), "l"(b));
}
__device__ __forceinline__ float2 unpack2(u64 v) {
    float2 f; asm("mov.b64 {%0, %1}, %2;" : "=f"(f.x), "=f"(f.y) : "l"(v)); return f;
}

// =====================================================================
// GEMM: C[M x 128] = X[M x 128] @ Weff (+bias for MODE 0)
// MODE 0: Weff[k][c] = W[k][c] - W[128+k][c], C += bias[c]
// MODE 1: Weff[k][c] = W[128+k][c]
// 256 threads, 128-row block tile, 8x8 microtile, f32x2 FMA.
// dyn smem: Ws 128*128 + Xs 32*132
// =====================================================================
template<int MODE>
__global__ __launch_bounds__(256)
void gemm_dec(const float* __restrict__ X, const float* __restrict__ W,
              const float* __restrict__ bias, float* __restrict__ C)
{
    extern __shared__ float sm[];
    float* Ws = sm;              // 16384
    float* Xs = sm + 16384;      // 32*132 transposed [k][row]
    const int tid = threadIdx.x;
    const int tx = tid & 15, ty = tid >> 4;
    const size_t row0 = (size_t)blockIdx.x * 128;

    // stage Weff
    #pragma unroll
    for (int e = 0; e < 16; e++) {
        int i4 = tid + e * 256;                    // float4 index into 128x128
        float4 w;
        if (MODE == 0) {
            w = ((const float4*)W)[i4];
            float4 w2 = ((const float4*)W)[i4 + 4096];
            w.x -= w2.x; w.y -= w2.y; w.z -= w2.z; w.w -= w2.w;
        } else {
            w = ((const float4*)W)[i4 + 4096];
        }
        ((float4*)Ws)[i4] = w;
    }

    u64 acc[8][4];
    #pragma unroll
    for (int i = 0; i < 8; i++)
        #pragma unroll
        for (int j = 0; j < 4; j++) acc[i][j] = 0ull;

    for (int kc = 0; kc < 4; kc++) {
        __syncthreads();
        // stage X chunk transposed: 128 rows x 32 k
        #pragma unroll
        for (int e = 0; e < 4; e++) {
            int t = tid + e * 256;                 // 0..1023
            int row = t >> 3;
            int kq  = (t & 7) * 4;
            float4 v = *(const float4*)&X[(row0 + row) * 128 + kc * 32 + kq];
            Xs[(kq + 0) * 132 + row] = v.x;
            Xs[(kq + 1) * 132 + row] = v.y;
            Xs[(kq + 2) * 132 + row] = v.z;
            Xs[(kq + 3) * 132 + row] = v.w;
        }
        __syncthreads();
        #pragma unroll 8
        for (int kk = 0; kk < 32; kk++) {
            const float* xrow = &Xs[kk * 132 + ty * 8];
            float4 a0 = *(const float4*)xrow;
            float4 a1 = *(const float4*)(xrow + 4);
            const u64* brow = (const u64*)&Ws[(kc * 32 + kk) * 128 + tx * 8];
            u64 b0 = brow[0], b1 = brow[1], b2 = brow[2], b3 = brow[3];
            u64 s;
            s = splat2(a0.x); ffma2(acc[0][0],s,b0); ffma2(acc[0][1],s,b1); ffma2(acc[0][2],s,b2); ffma2(acc[0][3],s,b3);
            s = splat2(a0.y); ffma2(acc[1][0],s,b0); ffma2(acc[1][1],s,b1); ffma2(acc[1][2],s,b2); ffma2(acc[1][3],s,b3);
            s = splat2(a0.z); ffma2(acc[2][0],s,b0); ffma2(acc[2][1],s,b1); ffma2(acc[2][2],s,b2); ffma2(acc[2][3],s,b3);
            s = splat2(a0.w); ffma2(acc[3][0],s,b0); ffma2(acc[3][1],s,b1); ffma2(acc[3][2],s,b2); ffma2(acc[3][3],s,b3);
            s = splat2(a1.x); ffma2(acc[4][0],s,b0); ffma2(acc[4][1],s,b1); ffma2(acc[4][2],s,b2); ffma2(acc[4][3],s,b3);
            s = splat2(a1.y); ffma2(acc[5][0],s,b0); ffma2(acc[5][1],s,b1); ffma2(acc[5][2],s,b2); ffma2(acc[5][3],s,b3);
            s = splat2(a1.z); ffma2(acc[6][0],s,b0); ffma2(acc[6][1],s,b1); ffma2(acc[6][2],s,b2); ffma2(acc[6][3],s,b3);
            s = splat2(a1.w); ffma2(acc[7][0],s,b0); ffma2(acc[7][1],s,b1); ffma2(acc[7][2],s,b2); ffma2(acc[7][3],s,b3);
        }
    }

    float4 bv0 = {0.f,0.f,0.f,0.f}, bv1 = bv0;
    if (MODE == 0) {
        bv0 = *(const float4*)&bias[tx * 8];
        bv1 = *(const float4*)&bias[tx * 8 + 4];
    }
    #pragma unroll
    for (int i = 0; i < 8; i++) {
        float2 p0 = unpack2(acc[i][0]), p1 = unpack2(acc[i][1]);
        float2 p2 = unpack2(acc[i][2]), p3 = unpack2(acc[i][3]);
        float4 o0 = {p0.x + bv0.x, p0.y + bv0.y, p1.x + bv0.z, p1.y + bv0.w};
        float4 o1 = {p2.x + bv1.x, p2.y + bv1.y, p3.x + bv1.z, p3.y + bv1.w};
        size_t r = row0 + ty * 8 + i;
        *(float4*)&C[r * 128 + tx * 8]     = o0;
        *(float4*)&C[r * 128 + tx * 8 + 4] = o1;
    }
}

// =====================================================================
// Fused 2-layer MLP: Y = relu( elu(X@W1+b1) @ W2 + b2 )
// 128-row blocks. Layer-1 output written transposed into smem, then the
// f32x2 GEMM core consumes it directly.
// =====================================================================
template<int IN>
__global__ __launch_bounds__(256)
void mlp2(const float* __restrict__ X,
          const float* __restrict__ W1, const float* __restrict__ b1,
          const float* __restrict__ W2, const float* __restrict__ b2,
          float* __restrict__ Y)
{
    extern __shared__ float sm[];
    float* Ws  = sm;                   // 16384
    float* Hs  = Ws + 16384;           // 128*132 transposed [c][r]
    float* Xin = Hs + 128 * 132;       // 128*IN
    float* W1s = Xin + 128 * IN;       // IN*128
    float* b1s = W1s + IN * 128;       // 128
    const int tid = threadIdx.x;
    const int tx = tid & 15, ty = tid >> 4;
    const size_t row0 = (size_t)blockIdx.x * 128;

    #pragma unroll
    for (int e = 0; e < 16; e++)
        ((float4*)Ws)[tid + e * 256] = ((const float4*)W2)[tid + e * 256];
    for (int t = tid; t < 128 * IN; t += 256) Xin[t] = X[row0 * IN + t];
    for (int t = tid; t < IN * 128; t += 256) W1s[t] = W1[t];
    if (tid < 128) b1s[tid] = b1[tid];
    __syncthreads();

    // layer 1: each thread one row-half
    {
        int r = tid >> 1, ch = (tid & 1) * 64;
        float xr[IN];
        #pragma unroll
        for (int d = 0; d < IN; d++) xr[d] = Xin[r * IN + d];
        #pragma unroll 4
        for (int cc = 0; cc < 64; cc++) {
            int c = ch + cc;
            float a = b1s[c];
            #pragma unroll
            for (int d = 0; d < IN; d++) a = fmaf(xr[d], W1s[d * 128 + c], a);
            Hs[c * 132 + r] = eluf(a);
        }
    }
    __syncthreads();

    u64 acc[8][4];
    #pragma unroll
    for (int i = 0; i < 8; i++)
        #pragma unroll
        for (int j = 0; j < 4; j++) acc[i][j] = 0ull;

    #pragma unroll 8
    for (int kk = 0; kk < 128; kk++) {
        const float* xrow = &Hs[kk * 132 + ty * 8];
        float4 a0 = *(const float4*)xrow;
        float4 a1 = *(const float4*)(xrow + 4);
        const u64* brow = (const u64*)&Ws[kk * 128 + tx * 8];
        u64 b0 = brow[0], b1v = brow[1], b2v = brow[2], b3v = brow[3];
        u64 s;
        s = splat2(a0.x); ffma2(acc[0][0],s,b0); ffma2(acc[0][1],s,b1v); ffma2(acc[0][2],s,b2v); ffma2(acc[0][3],s,b3v);
        s = splat2(a0.y); ffma2(acc[1][0],s,b0); ffma2(acc[1][1],s,b1v); ffma2(acc[1][2],s,b2v); ffma2(acc[1][3],s,b3v);
        s = splat2(a0.z); ffma2(acc[2][0],s,b0); ffma2(acc[2][1],s,b1v); ffma2(acc[2][2],s,b2v); ffma2(acc[2][3],s,b3v);
        s = splat2(a0.w); ffma2(acc[3][0],s,b0); ffma2(acc[3][1],s,b1v); ffma2(acc[3][2],s,b2v); ffma2(acc[3][3],s,b3v);
        s = splat2(a1.x); ffma2(acc[4][0],s,b0); ffma2(acc[4][1],s,b1v); ffma2(acc[4][2],s,b2v); ffma2(acc[4][3],s,b3v);
        s = splat2(a1.y); ffma2(acc[5][0],s,b0); ffma2(acc[5][1],s,b1v); ffma2(acc[5][2],s,b2v); ffma2(acc[5][3],s,b3v);
        s = splat2(a1.z); ffma2(acc[6][0],s,b0); ffma2(acc[6][1],s,b1v); ffma2(acc[6][2],s,b2v); ffma2(acc[6][3],s,b3v);
        s = splat2(a1.w); ffma2(acc[7][0],s,b0); ffma2(acc[7][1],s,b1v); ffma2(acc[7][2],s,b2v); ffma2(acc[7][3],s,b3v);
    }

    float4 c0 = *(const float4*)&b2[tx * 8];
    float4 c1 = *(const float4*)&b2[tx * 8 + 4];
    #pragma unroll
    for (int i = 0; i < 8; i++) {
        float2 p0 = unpack2(acc[i][0]), p1 = unpack2(acc[i][1]);
        float2 p2 = unpack2(acc[i][2]), p3 = unpack2(acc[i][3]);
        float4 o0 = {fmaxf(p0.x + c0.x, 0.f), fmaxf(p0.y + c0.y, 0.f),
                     fmaxf(p1.x + c0.z, 0.f), fmaxf(p1.y + c0.w, 0.f)};
        float4 o1 = {fmaxf(p2.x + c1.x, 0.f), fmaxf(p2.y + c1.y, 0.f),
                     fmaxf(p3.x + c1.z, 0.f), fmaxf(p3.y + c1.w, 0.f)};
        size_t r = row0 + ty * 8 + i;
        *(float4*)&Y[r * 128 + tx * 8]     = o0;
        *(float4*)&Y[r * 128 + tx * 8 + 4] = o1;
    }
}

// =====================================================================
// Edge conv: kNN over scores (||s||^2 - 2 d.s), gather-max of V, ELU.
// HEAD=true additionally fuses mean-pooling + output MLP (no f2 store).
// One block per graph, 256 threads.
// =====================================================================
template<int NSRC, bool HEAD>
__global__ __launch_bounds__(256)
void edgeconv(const float* __restrict__ dstF, const float* __restrict__ srcF,
              const float* __restrict__ U,    const float* __restrict__ V,
              float* __restrict__ fout,
              const float* __restrict__ Wo1, const float* __restrict__ bo1,
              const float* __restrict__ Wo2, const float* __restrict__ bo2,
              const float* __restrict__ Wo3, const float* __restrict__ bo3,
              const float* __restrict__ Wo4, const float* __restrict__ bo4,
              float* __restrict__ out, int out_size)
{
    extern __shared__ float sm[];
    float* dsh = sm;                        // 64*130
    float* ssh = dsh + 64 * 130;            // NSRC*130
    float* vsh = ssh + NSRC * 130;          // NSRC*130
    float* sc  = vsh + NSRC * 130;          // 64*(NSRC+1)
    float* sn2 = sc + 64 * (NSRC + 1);      // NSRC
    float* colsum = sn2 + NSRC;             // 256
    float* pooled = colsum + 256;           // 128
    float* h1 = pooled + 128;               // 64
    float* h2 = h1 + 64;                    // 32
    float* h3 = h2 + 32;                    // 4
    int*  idxs = (int*)(h3 + 4);            // 64*8

    const int g   = blockIdx.x;
    const int tid = threadIdx.x;
    const float* dg = dstF + (size_t)g * 64 * 128;
    const float* sg = srcF + (size_t)g * NSRC * 128;
    const float* Vg = V    + (size_t)g * NSRC * 128;
    const float* Ug = U    + (size_t)g * 64 * 128;

    for (int t = tid; t < 64 * 128; t += 256)
        dsh[(t >> 7) * 130 + (t & 127)] = dg[t];
    for (int t = tid; t < NSRC * 128; t += 256) {
        int r = t >> 7, c = t & 127;
        ssh[r * 130 + c] = sg[t];
        vsh[r * 130 + c] = Vg[t];
    }
    __syncthreads();

    if (tid < NSRC) {
        float s = 0.f;
        #pragma unroll 8
        for (int d = 0; d < 128; d++) { float v = ssh[tid * 130 + d]; s += v * v; }
        sn2[tid] = s;
    }
    __syncthreads();

    // scores = ||src_j||^2 - 2 * dot(dst_i, src_j)  (ranking-equivalent to d2)
    const int tx = tid & 15, ty = tid >> 4;
    if (NSRC == 64) {
        u64 acc[4][4];
        #pragma unroll
        for (int a = 0; a < 4; a++)
            #pragma unroll
            for (int b = 0; b < 4; b++) acc[a][b] = 0ull;
        #pragma unroll 8
        for (int kk = 0; kk < 64; kk++) {
            u64 av[4], bv[4];
            #pragma unroll
            for (int ii = 0; ii < 4; ii++) av[ii] = *(const u64*)&dsh[(ty * 4 + ii) * 130 + kk * 2];
            #pragma unroll
            for (int jj = 0; jj < 4; jj++) bv[jj] = *(const u64*)&ssh[(tx * 4 + jj) * 130 + kk * 2];
            #pragma unroll
            for (int ii = 0; ii < 4; ii++)
                #pragma unroll
                for (int jj = 0; jj < 4; jj++) ffma2(acc[ii][jj], av[ii], bv[jj]);
        }
        #pragma unroll
        for (int ii = 0; ii < 4; ii++)
            #pragma unroll
            for (int jj = 0; jj < 4; jj++) {
                float2 p = unpack2(acc[ii][jj]);
                int i = ty * 4 + ii, j = tx * 4 + jj;
                sc[i * (NSRC + 1) + j] = sn2[j] - 2.f * (p.x + p.y);
            }
    } else {  // NSRC == 16
        u64 acc[4];
        #pragma unroll
        for (int a = 0; a < 4; a++) acc[a] = 0ull;
        #pragma unroll 8
        for (int kk = 0; kk < 64; kk++) {
            u64 bv = *(const u64*)&ssh[tx * 130 + kk * 2];
            #pragma unroll
            for (int ii = 0; ii < 4; ii++) {
                u64 av = *(const u64*)&dsh[(ty * 4 + ii) * 130 + kk * 2];
                ffma2(acc[ii], av, bv);
            }
        }
        #pragma unroll
        for (int ii = 0; ii < 4; ii++) {
            float2 p = unpack2(acc[ii]);
            sc[(ty * 4 + ii) * (NSRC + 1) + tx] = sn2[tx] - 2.f * (p.x + p.y);
        }
    }
    __syncthreads();

    // top-8 smallest (tie -> lowest index, matching lax.top_k)
    if (tid < 64) {
        const float* row = &sc[tid * (NSRC + 1)];
        u64 used = 0ull;
        #pragma unroll
        for (int n = 0; n < KNN; n++) {
            float best = FLT_MAX; int bj = 0;
            for (int j = 0; j < NSRC; j++) {
                if ((used >> j) & 1ull) continue;
                float v = row[j];
                if (v < best) { best = v; bj = j; }
            }
            used |= 1ull << bj;
            idxs[tid * 8 + n] = bj;
        }
    }
    __syncthreads();

    // combine: elu(U(+bias already) + max_n V[idx])
    int c = tid & 127, ih = tid >> 7;
    float csum = 0.f;
    for (int i0 = 0; i0 < 64; i0 += 2) {
        int i = i0 + ih;
        const int* ip = &idxs[i * 8];
        float vmax = -FLT_MAX;
        #pragma unroll
        for (int n = 0; n < KNN; n++) vmax = fmaxf(vmax, vsh[ip[n] * 130 + c]);
        float val = eluf(Ug[i * 128 + c] + vmax);
        if (HEAD) csum += val;
        else      fout[((size_t)g * 64 + i) * 128 + c] = val;
    }

    if (HEAD) {
        colsum[ih * 128 + c] = csum;
        __syncthreads();
        if (tid < 128) pooled[tid] = (colsum[tid] + colsum[128 + tid]) * (1.f / 64.f);
        __syncthreads();
        if (tid < 64) {
            float a = bo1[tid];
            #pragma unroll 8
            for (int d = 0; d < 128; d++) a += pooled[d] * Wo1[d * 64 + tid];
            h1[tid] = eluf(a);
        }
        __syncthreads();
        if (tid < 32) {
            float a = bo2[tid];
            #pragma unroll 8
            for (int d = 0; d < 64; d++) a += h1[d] * Wo2[d * 32 + tid];
            h2[tid] = eluf(a);
        }
        __syncthreads();
        if (tid < 4) {
            float a = bo3[tid];
            #pragma unroll
            for (int d = 0; d < 32; d++) a += h2[d] * Wo3[d * 4 + tid];
            h3[tid] = eluf(a);
        }
        __syncthreads();
        if (tid == 0) {
            float a = bo4[0];
            #pragma unroll
            for (int d = 0; d < 4; d++) a += h3[d] * Wo4[d];
            out[g] = a;
            if (out_size >= 2 * G) out[G + g] = (float)g;
        }
    }
}

// ---------------- launch ----------------
extern "C" void kernel_launch(void* const* d_in, const int* in_sizes, int n_in,
                              void* d_out, int out_size)
{
    const float* x_sv   = (const float*)d_in[0];
    const float* x_trk  = (const float*)d_in[1];
    const float* W_sv1  = (const float*)d_in[2];
    const float* b_sv1  = (const float*)d_in[3];
    const float* W_sv2  = (const float*)d_in[4];
    const float* b_sv2  = (const float*)d_in[5];
    const float* W_trk1 = (const float*)d_in[6];
    const float* b_trk1 = (const float*)d_in[7];
    const float* W_trk2 = (const float*)d_in[8];
    const float* b_trk2 = (const float*)d_in[9];
    const float* W_c1   = (const float*)d_in[10];
    const float* b_c1   = (const float*)d_in[11];
    const float* W_c2   = (const float*)d_in[12];
    const float* b_c2   = (const float*)d_in[13];
    const float* W_o1   = (const float*)d_in[14];
    const float* b_o1   = (const float*)d_in[15];
    const float* W_o2   = (const float*)d_in[16];
    const float* b_o2   = (const float*)d_in[17];
    const float* W_o3   = (const float*)d_in[18];
    const float* b_o3   = (const float*)d_in[19];
    const float* W_o4   = (const float*)d_in[20];
    const float* b_o4   = (const float*)d_in[21];
    float* out = (float*)d_out;

    float *p_sv, *p_trk, *p_U1, *p_U2, *p_V1, *p_V2, *p_f1;
    cudaGetSymbolAddress((void**)&p_sv,  g_sv);
    cudaGetSymbolAddress((void**)&p_trk, g_trk);
    cudaGetSymbolAddress((void**)&p_U1,  g_U1);
    cudaGetSymbolAddress((void**)&p_U2,  g_U2);
    cudaGetSymbolAddress((void**)&p_V1,  g_V1);
    cudaGetSymbolAddress((void**)&p_V2,  g_V2);
    cudaGetSymbolAddress((void**)&p_f1,  g_f1);

    const int smem_gemm = (16384 + 32 * 132) * 4;
    const int smem_mlp8 = (16384 + 128 * 132 + 128 * 8 + 8 * 128 + 128) * 4;
    const int smem_mlp2 = (16384 + 128 * 132 + 128 * 2 + 2 * 128 + 128) * 4;
    auto conv_smem = [](int nsrc) {
        return (64 * 130 + 2 * nsrc * 130 + 64 * (nsrc + 1) + nsrc
                + 256 + 128 + 64 + 32 + 4) * 4 + 64 * 8 * 4;
    };
    const int smem_c1 = conv_smem(NSV);
    const int smem_c2 = conv_smem(NTRK);

    (void)cudaFuncSetAttribute(gemm_dec<0>, cudaFuncAttributeMaxDynamicSharedMemorySize, smem_gemm);
    (void)cudaFuncSetAttribute(gemm_dec<1>, cudaFuncAttributeMaxDynamicSharedMemorySize, smem_gemm);
    (void)cudaFuncSetAttribute(mlp2<8>,     cudaFuncAttributeMaxDynamicSharedMemorySize, smem_mlp8);
    (void)cudaFuncSetAttribute(mlp2<2>,     cudaFuncAttributeMaxDynamicSharedMemorySize, smem_mlp2);
    (void)cudaFuncSetAttribute((const void*)edgeconv<NSV,  false>, cudaFuncAttributeMaxDynamicSharedMemorySize, smem_c1);
    (void)cudaFuncSetAttribute((const void*)edgeconv<NTRK, true>,  cudaFuncAttributeMaxDynamicSharedMemorySize, smem_c2);

    // node MLPs
    mlp2<2><<<G * NSV  / 128, 256, smem_mlp2>>>(x_sv,  W_sv1,  b_sv1,  W_sv2,  b_sv2,  p_sv);
    mlp2<8><<<G * NTRK / 128, 256, smem_mlp8>>>(x_trk, W_trk1, b_trk1, W_trk2, b_trk2, p_trk);

    // U/V transforms (U includes conv bias)
    gemm_dec<0><<<G * NTRK / 128, 256, smem_gemm>>>(p_trk, W_c1, b_c1, p_U1);
    gemm_dec<1><<<G * NSV  / 128, 256, smem_gemm>>>(p_sv,  W_c1, nullptr, p_V1);
    gemm_dec<0><<<G * NTRK / 128, 256, smem_gemm>>>(p_trk, W_c2, b_c2, p_U2);

    // conv1 -> f1
    edgeconv<NSV, false><<<G, 256, smem_c1>>>(p_trk, p_sv, p_U1, p_V1, p_f1,
        nullptr, nullptr, nullptr, nullptr, nullptr, nullptr, nullptr, nullptr,
        nullptr, 0);

    // V2 = f1 @ Wc2_bot
    gemm_dec<1><<<G * NTRK / 128, 256, smem_gemm>>>(p_f1, W_c2, nullptr, p_V2);

    // conv2 + pooled head (fused), writes final output
    edgeconv<NTRK, true><<<G, 256, smem_c2>>>(p_trk, p_f1, p_U2, p_V2, nullptr,
        W_o1, b_o1, W_o2, b_o2, W_o3, b_o3, W_o4, b_o4,
        out, out_size);
}